// round 10
// baseline (speedup 1.0000x reference)
#include <cuda_runtime.h>
#include <cuda_bf16.h>
#include <math.h>
#include <stdint.h>

// Problem constants
#define BB    16
#define CIN   128
#define COUT  256
#define HH    80
#define WW    80
#define KK9   9
#define HO    40
#define WO    40
#define NP    1600
#define RED   1152            // CIN*KK9
#define NT    64              // positions per CTA
#define NPT   25              // position tiles per batch
#define NCHUNK 18             // 9 taps x 2 channel-halves of 64
#define ROWB  144             // padded row pitch bytes (72 bf16)
#define ATILEB (128*ROWB)     // 18432 B (one hi or lo A half)
#define BTILEB (NT*ROWB)      // 9216 B
#define ABUF  (2*ATILEB)      // 36864 B per A buffer (hi+lo)
#define BBUF  (2*BTILEB)      // 18432 B per B buffer (hi+lo)

// smem layout (bytes): A0, A1, B0, B1, params
#define SM_A0   0
#define SM_A1   ABUF                       // 36864
#define SM_B0   (2*ABUF)                   // 73728
#define SM_B1   (2*ABUF + BBUF)            // 92160
#define SM_PAR  (2*ABUF + 2*BBUF)          // 110592
#define SM_TOTAL (SM_PAR + KK9*NT*16)      // 119808

// named barriers
#define BAR_FULL0 1
#define BAR_FULL1 2
#define BAR_FREE0 3
#define BAR_FREE1 4

// ---------------- device scratch ----------------
__device__ float          g_xT[BB*HH*WW*CIN];          // NHWC input
__device__ __nv_bfloat16  g_wA[NCHUNK*2*2*128*72];     // [q][mh][hi/lo][o][72]
__device__ float4         g_params[BB*NP*KK9];
__device__ float          g_pre[BB*COUT*NP];
__device__ float2         g_ps[BB*NPT*COUT];
__device__ float          g_bn[2*COUT];

// ---------------- PTX helpers (baseline sm_103-legal) ----------------
__device__ __forceinline__ uint32_t smem_u32(const void* p) {
    uint32_t a;
    asm("{ .reg .u64 t; cvta.to.shared.u64 t, %1; cvt.u32.u64 %0, t; }" : "=r"(a) : "l"(p));
    return a;
}
__device__ __forceinline__ void ldsm4(uint32_t* r, uint32_t addr) {
    asm volatile("ldmatrix.sync.aligned.m8n8.x4.shared.b16 {%0,%1,%2,%3}, [%4];"
        : "=r"(r[0]), "=r"(r[1]), "=r"(r[2]), "=r"(r[3]) : "r"(addr));
}
__device__ __forceinline__ void mma16816(float* d, const uint32_t* a, uint32_t b0, uint32_t b1) {
    asm volatile("mma.sync.aligned.m16n8k16.row.col.f32.bf16.bf16.f32 "
        "{%0,%1,%2,%3}, {%4,%5,%6,%7}, {%8,%9}, {%0,%1,%2,%3};"
        : "+f"(d[0]), "+f"(d[1]), "+f"(d[2]), "+f"(d[3])
        : "r"(a[0]), "r"(a[1]), "r"(a[2]), "r"(a[3]), "r"(b0), "r"(b1));
}
__device__ __forceinline__ void cpa16(uint32_t dst, const void* src) {
    asm volatile("cp.async.cg.shared.global [%0], [%1], 16;" :: "r"(dst), "l"(src));
}
__device__ __forceinline__ void cpa_commit() {
    asm volatile("cp.async.commit_group;" ::: "memory");
}
template <int N>
__device__ __forceinline__ void cpa_wait() {
    asm volatile("cp.async.wait_group %0;" :: "n"(N) : "memory");
}
__device__ __forceinline__ void bar_sync(int id) {
    asm volatile("bar.sync %0, %1;" :: "r"(id), "r"(256) : "memory");
}
__device__ __forceinline__ void bar_arrive(int id) {
    asm volatile("bar.arrive %0, %1;" :: "r"(id), "r"(256) : "memory");
}

// ---------------- K0: vectorized tiled transpose (B,C,H,W)->(B,H,W,C) ----------------
__global__ __launch_bounds__(256) void k_transpose(const float* __restrict__ x) {
    int b = blockIdx.x / HH;
    int y = blockIdx.x % HH;
    __shared__ float4 s4[CIN*21];
    const float4* src = (const float4*)(x + ((size_t)b*CIN)*HH*WW + (size_t)y*WW);
    int tid = threadIdx.x;
    #pragma unroll
    for (int i = 0; i < 10; i++) {
        int idx = tid + i*256;
        int c = idx / 20, w4 = idx % 20;
        s4[c*21 + w4] = src[(size_t)c*1600 + w4];
    }
    __syncthreads();
    const float* sf = (const float*)s4;
    float4* dst = (float4*)&g_xT[((size_t)(b*HH + y))*WW*CIN];
    #pragma unroll
    for (int i = 0; i < 10; i++) {
        int idx = tid + i*256;
        int w  = idx >> 5;
        int c4 = (idx & 31)*4;
        int base = w >> 2, wm = (w & 3);
        float4 v;
        v.x = sf[(c4+0)*84 + base*4 + wm];
        v.y = sf[(c4+1)*84 + base*4 + wm];
        v.z = sf[(c4+2)*84 + base*4 + wm];
        v.w = sf[(c4+3)*84 + base*4 + wm];
        dst[idx] = v;
    }
}

// ---------------- K0b: weight prep -> padded bf16 hi/lo tiles ----------------
__global__ void k_wprep(const float* __restrict__ w) {
    int i = blockIdx.x*256 + threadIdx.x;
    if (i >= NCHUNK*2*2*128*72) return;
    int u  = i % 72;
    int t1 = i / 72;
    int o  = t1 & 127;
    int t2 = t1 >> 7;
    int hl = t2 & 1;
    int t3 = t2 >> 1;
    int mh = t3 & 1;
    int q  = t3 >> 1;
    __nv_bfloat16 outv = __float2bfloat16(0.f);
    if (u < 64) {
        int tap = q >> 1;
        int c   = ((q & 1) << 6) | u;
        float v = w[(size_t)(mh*128 + o)*RED + c*KK9 + tap];
        __nv_bfloat16 h = __float2bfloat16(v);
        outv = hl ? __float2bfloat16(v - __bfloat162float(h)) : h;
    }
    g_wA[i] = outv;
}

// ---------------- K1: offsets + bilinear params ----------------
__global__ void k_offsets(const float* __restrict__ offw, const float* __restrict__ offb) {
    int gw   = (blockIdx.x * blockDim.x + threadIdx.x) >> 5;
    int lane = threadIdx.x & 31;
    if (gw >= BB*NP) return;
    int b = gw / NP, p = gw % NP;
    int ho = p / WO, wo = p % WO;

    const float4* xs = (const float4*)&g_xT[(((size_t)b*HH + 2*ho)*WW + 2*wo)*CIN];
    float4 xv = xs[lane];

    float dy = 0.f, dx = 0.f;
    #pragma unroll
    for (int j = 0; j < 18; j++) {
        const float* wr = offw + j*CIN + lane*4;
        float s = wr[0]*xv.x + wr[1]*xv.y + wr[2]*xv.z + wr[3]*xv.w;
        #pragma unroll
        for (int d = 16; d > 0; d >>= 1) s += __shfl_xor_sync(0xffffffffu, s, d);
        if (lane < 9) {
            if (j == 2*lane)     dy = s;
            if (j == 2*lane + 1) dx = s;
        }
    }
    if (lane < 9) {
        int k = lane;
        dy += __ldg(&offb[2*k]);
        dx += __ldg(&offb[2*k+1]);
        float py = (float)(ho*2 - 1 + k/3) + dy;
        float px = (float)(wo*2 - 1 + k%3) + dx;
        float fy = floorf(py), fx = floorf(px);
        int y0 = (int)fy, x0 = (int)fx;
        g_params[(size_t)gw*KK9 + k] =
            make_float4(__int_as_float(y0), __int_as_float(x0), py - fy, px - fx);
    }
}

// ---------------- K2: main — warp-specialized producer/consumer ----------------
// 800 CTAs: (b, ptile of 64, mhalf). 8 warps: 0-3 MMA consumers (m32 x n64 each),
// 4-7 producers (gather + bf16 split + STS + A cp.async). 2-deep ping-pong.
__global__ __launch_bounds__(256, 1) void k_main(const float* __restrict__ deform_b) {
    extern __shared__ __align__(16) unsigned char sm[];
    uint32_t sb = smem_u32(sm);
    int tid  = threadIdx.x;
    int wid  = tid >> 5;
    int lane = tid & 31;
    int bid  = blockIdx.x;
    int mh   = bid & 1;
    int pt   = (bid >> 1) % NPT;
    int b    = bid / (2*NPT);

    float4* spb = (float4*)(sm + SM_PAR);   // [tap][pos]

    // params for all 9 taps x 64 positions (all threads)
    for (int i = tid; i < KK9*NT; i += 256) {
        int p = i / KK9, tap = i - p*KK9;
        spb[tap*NT + p] = g_params[((size_t)b*NP + pt*NT + p)*KK9 + tap];
    }
    __syncthreads();

    if (wid >= 4) {
        // ================= PRODUCER =================
        int ptid = tid - 128;
        int c16  = ptid & 15;        // 4-channel group
        int pst  = ptid >> 4;        // 0..7
        const float* xb = &g_xT[(size_t)b*HH*WW*CIN];

        #pragma unroll 1
        for (int q = 0; q < NCHUNK; q++) {
            int par = q & 1;
            if (q >= 2) bar_sync(BAR_FREE0 + par);

            // A(q) -> A[par] via cp.async (overlaps with gather below)
            {
                const char* asrc = (const char*)g_wA + (size_t)(q*2 + mh)*ABUF;
                uint32_t adst = sb + (par ? SM_A1 : SM_A0);
                #pragma unroll
                for (int i = 0; i < 18; i++) {
                    uint32_t off = (uint32_t)(ptid + i*128)*16;
                    cpa16(adst + off, asrc + off);
                }
                cpa_commit();
            }

            // gather + convert + STS into B[par]
            int cb = ((q & 1) << 6) + c16*4;
            const float4* sp_tap = (const float4*)&spb[(q >> 1)*NT];
            unsigned char* bbase = sm + (par ? SM_B1 : SM_B0);
            #pragma unroll 2
            for (int it = 0; it < 8; it++) {
                int p = pst + it*8;
                float4 pr = sp_tap[p];
                int y0 = __float_as_int(pr.x);
                int x0 = __float_as_int(pr.y);
                float wy1 = pr.z, wx1 = pr.w;
                float wy0 = 1.f - wy1, wx0 = 1.f - wx1;
                int y1 = y0 + 1, x1 = x0 + 1;
                bool vy0 = ((unsigned)y0 < (unsigned)HH);
                bool vy1 = ((unsigned)y1 < (unsigned)HH);
                bool vx0 = ((unsigned)x0 < (unsigned)WW);
                bool vx1 = ((unsigned)x1 < (unsigned)WW);
                int yc0 = min(max(y0, 0), HH-1), yc1 = min(max(y1, 0), HH-1);
                int xc0 = min(max(x0, 0), WW-1), xc1 = min(max(x1, 0), WW-1);
                const float4 z4 = make_float4(0.f, 0.f, 0.f, 0.f);
                float4 g00 = (vy0 && vx0) ? *(const float4*)(xb + ((size_t)yc0*WW + xc0)*CIN + cb) : z4;
                float4 g01 = (vy0 && vx1) ? *(const float4*)(xb + ((size_t)yc0*WW + xc1)*CIN + cb) : z4;
                float4 g10 = (vy1 && vx0) ? *(const float4*)(xb + ((size_t)yc1*WW + xc0)*CIN + cb) : z4;
                float4 g11 = (vy1 && vx1) ? *(const float4*)(xb + ((size_t)yc1*WW + xc1)*CIN + cb) : z4;
                float w00 = wy0*wx0, w01 = wy0*wx1, w10 = wy1*wx0, w11 = wy1*wx1;
                float v0 = w00*g00.x + w01*g01.x + w10*g10.x + w11*g11.x;
                float v1 = w00*g00.y + w01*g01.y + w10*g10.y + w11*g11.y;
                float v2 = w00*g00.z + w01*g01.z + w10*g10.z + w11*g11.z;
                float v3 = w00*g00.w + w01*g01.w + w10*g10.w + w11*g11.w;
                __nv_bfloat16 h0 = __float2bfloat16(v0), h1 = __float2bfloat16(v1);
                __nv_bfloat16 h2 = __float2bfloat16(v2), h3 = __float2bfloat16(v3);
                float l0 = v0 - __bfloat162float(h0), l1 = v1 - __bfloat162float(h1);
                float l2 = v2 - __bfloat162float(h2), l3 = v3 - __bfloat162float(h3);
                unsigned long long hv =
                    (unsigned long long)__bfloat16_as_ushort(h0)
                  | ((unsigned long long)__bfloat16_as_ushort(h1) << 16)
                  | ((unsigned long long)__bfloat16_as_ushort(h2) << 32)
                  | ((unsigned long long)__bfloat16_as_ushort(h3) << 48);
                unsigned long long lv =
                    (unsigned long long)__bfloat16_as_ushort(__float2bfloat16(l0))
                  | ((unsigned long long)__bfloat16_as_ushort(__float2bfloat16(l1)) << 16)
                  | ((unsigned long long)__bfloat16_as_ushort(__float2bfloat16(l2)) << 32)
                  | ((unsigned long long)__bfloat16_as_ushort(__float2bfloat16(l3)) << 48);
                uint32_t off = (uint32_t)p*ROWB + c16*8;
                *(unsigned long long*)(bbase + off) = hv;
                *(unsigned long long*)(bbase + BTILEB + off) = lv;
            }
            cpa_wait<0>();                 // A(q) landed
            bar_arrive(BAR_FULL0 + par);   // hand buffer to consumers
        }
    } else {
        // ================= CONSUMER =================
        int wm = wid;   // m32 rows each; n64 full width

        uint32_t aadr0 = sb + SM_A0 + (uint32_t)(wm*32 + (lane & 15))*ROWB + ((lane >> 4) & 1)*16;
        uint32_t aadr1 = aadr0 + 16*ROWB;
        uint32_t badr  = sb + SM_B0 + (uint32_t)((lane & 7) + ((lane >> 4) & 1)*8)*ROWB
                       + ((lane >> 3) & 1)*16;

        float d[2][8][4];
        #pragma unroll
        for (int mf = 0; mf < 2; mf++)
            #pragma unroll
            for (int nf = 0; nf < 8; nf++)
                #pragma unroll
                for (int j = 0; j < 4; j++) d[mf][nf][j] = 0.f;

        #pragma unroll 1
        for (int q = 0; q < NCHUNK; q++) {
            int par = q & 1;
            bar_sync(BAR_FULL0 + par);     // wait for producer fill (A + B)
            uint32_t aoff = par ? ABUF : 0;
            uint32_t boff = par ? BBUF : 0;
            #pragma unroll
            for (int kf = 0; kf < 4; kf++) {
                uint32_t kb = kf*32;
                uint32_t Ah0[4], Ah1[4], Al0[4], Al1[4];
                ldsm4(Ah0, aadr0 + aoff + kb);
                ldsm4(Ah1, aadr1 + aoff + kb);
                ldsm4(Al0, aadr0 + aoff + ATILEB + kb);
                ldsm4(Al1, aadr1 + aoff + ATILEB + kb);
                uint32_t Bh[4][4], Bl[4][4];
                #pragma unroll
                for (int g = 0; g < 4; g++) {
                    ldsm4(Bh[g], badr + boff + (uint32_t)g*16*ROWB + kb);
                    ldsm4(Bl[g], badr + boff + BTILEB + (uint32_t)g*16*ROWB + kb);
                }
                #pragma unroll
                for (int mf = 0; mf < 2; mf++) {
                    const uint32_t* ah = mf ? Ah1 : Ah0;
                    const uint32_t* al = mf ? Al1 : Al0;
                    #pragma unroll
                    for (int g = 0; g < 4; g++) {
                        #pragma unroll
                        for (int h = 0; h < 2; h++) {
                            int nf = g*2 + h;
                            mma16816(d[mf][nf], ah, Bh[g][h*2], Bh[g][h*2+1]);
                            mma16816(d[mf][nf], ah, Bl[g][h*2], Bl[g][h*2+1]);
                            mma16816(d[mf][nf], al, Bh[g][h*2], Bh[g][h*2+1]);
                        }
                    }
                }
            }
            bar_arrive(BAR_FREE0 + par);   // release buffer to producers
        }

        // ---- epilogue: bias + store + BN partials ----
        int rbase = lane >> 2;
        int cpair = (lane & 3)*2;
        #pragma unroll
        for (int mf = 0; mf < 2; mf++) {
            #pragma unroll
            for (int rh = 0; rh < 2; rh++) {
                int o_loc = wm*32 + mf*16 + rh*8 + rbase;
                int o     = mh*128 + o_loc;
                float bias = __ldg(&deform_b[o]);
                float s1 = 0.f, s2 = 0.f;
                float* orow = &g_pre[((size_t)(b*COUT + o))*NP + pt*NT];
                #pragma unroll
                for (int nf = 0; nf < 8; nf++) {
                    float v0 = d[mf][nf][rh*2 + 0] + bias;
                    float v1 = d[mf][nf][rh*2 + 1] + bias;
                    *(float2*)&orow[nf*8 + cpair] = make_float2(v0, v1);
                    s1 += v0 + v1;
                    s2 += v0*v0 + v1*v1;
                }
                s1 += __shfl_xor_sync(0xffffffffu, s1, 1);
                s1 += __shfl_xor_sync(0xffffffffu, s1, 2);
                s2 += __shfl_xor_sync(0xffffffffu, s2, 1);
                s2 += __shfl_xor_sync(0xffffffffu, s2, 2);
                if ((lane & 3) == 0)
                    g_ps[((size_t)(b*NPT + pt))*COUT + o] = make_float2(s1, s2);
            }
        }
    }
}

// ---------------- K3: BN finalize (parallel, deterministic) ----------------
__global__ void k_bnfin(const float* __restrict__ gamma, const float* __restrict__ beta) {
    int o = blockIdx.x;
    int tid = threadIdx.x;     // 128
    double s = 0.0, s2 = 0.0;
    for (int t = tid; t < BB*NPT; t += 128) {
        float2 v = g_ps[(size_t)t*COUT + o];
        s  += (double)v.x;
        s2 += (double)v.y;
    }
    __shared__ double sh[128], sh2[128];
    sh[tid] = s; sh2[tid] = s2;
    __syncthreads();
    for (int dd = 64; dd > 0; dd >>= 1) {
        if (tid < dd) { sh[tid] += sh[tid+dd]; sh2[tid] += sh2[tid+dd]; }
        __syncthreads();
    }
    if (tid == 0) {
        const double N = (double)(BB*NP);
        double mean = sh[0] / N;
        double var  = sh2[0] / N - mean*mean;
        double inv  = 1.0 / sqrt(var + 1e-5);
        float scale = (float)((double)gamma[o] * inv);
        float shift = (float)((double)beta[o] - mean * (double)scale);
        g_bn[2*o]   = scale;
        g_bn[2*o+1] = shift;
    }
}

// ---------------- K4: fused BN + SiLU ----------------
__global__ void k_act(float* __restrict__ out) {
    int i = blockIdx.x*256 + threadIdx.x;
    const int NV = BB*COUT*NP/4;
    if (i >= NV) return;
    int e = i*4;
    int o = (e / NP) & (COUT-1);
    float sc = g_bn[2*o], sh = g_bn[2*o+1];
    float4 v = ((const float4*)g_pre)[i];
    float y0 = v.x*sc + sh;
    float y1 = v.y*sc + sh;
    float y2 = v.z*sc + sh;
    float y3 = v.w*sc + sh;
    v.x = y0 / (1.f + __expf(-y0));
    v.y = y1 / (1.f + __expf(-y1));
    v.z = y2 / (1.f + __expf(-y2));
    v.w = y3 / (1.f + __expf(-y3));
    ((float4*)out)[i] = v;
}

// ---------------- launch ----------------
extern "C" void kernel_launch(void* const* d_in, const int* in_sizes, int n_in,
                              void* d_out, int out_size) {
    const float* x        = (const float*)d_in[0];
    const float* offset_w = (const float*)d_in[1];
    const float* offset_b = (const float*)d_in[2];
    const float* deform_w = (const float*)d_in[3];
    const float* deform_b = (const float*)d_in[4];
    const float* bn_gamma = (const float*)d_in[5];
    const float* bn_beta  = (const float*)d_in[6];
    float* out = (float*)d_out;

    cudaFuncSetAttribute(k_main, cudaFuncAttributeMaxDynamicSharedMemorySize, SM_TOTAL);

    k_transpose<<<BB*HH, 256>>>(x);
    k_wprep<<<(NCHUNK*2*2*128*72 + 255)/256, 256>>>(deform_w);
    k_offsets<<<(BB*NP*32 + 127)/128, 128>>>(offset_w, offset_b);
    k_main<<<BB*NPT*2, 256, SM_TOTAL>>>(deform_b);
    k_bnfin<<<COUT, 128>>>(bn_gamma, bn_beta);
    k_act<<<(BB*COUT*NP/4 + 255)/256, 256>>>(out);
}

// round 11
// speedup vs baseline: 1.6880x; 1.6880x over previous
#include <cuda_runtime.h>
#include <cuda_bf16.h>
#include <math.h>
#include <stdint.h>

// Problem constants
#define BB    16
#define CIN   128
#define COUT  256
#define HH    80
#define WW    80
#define KK9   9
#define HO    40
#define WO    40
#define NP    1600
#define RED   1152            // CIN*KK9
#define NT    64              // positions per CTA
#define NPT   25              // position tiles per batch
#define NCTA2 (BB*NPT)        // 400
#define NCHUNK 18             // 9 taps x 2 channel-halves of 64
#define ROWB  144             // padded row pitch bytes (72 bf16)
#define ATILEB (256*ROWB)     // 36864 B (one hi or lo A tile, 256 rows)
#define BTILEB (NT*ROWB)      // 9216 B
#define ABUF  (2*ATILEB)      // 73728 B per A buffer (hi+lo)
#define BBUF  (2*BTILEB)      // 18432 B per B buffer (hi+lo)

// smem layout (bytes): A0, A1, B0, B1, params
#define SM_A0   0
#define SM_A1   ABUF                       // 73728
#define SM_B0   (2*ABUF)                   // 147456
#define SM_B1   (2*ABUF + BBUF)            // 165888
#define SM_PAR  (2*ABUF + 2*BBUF)          // 184320
#define SM_TOTAL (SM_PAR + KK9*NT*16)      // 193536 (189 KB)

// ---------------- device scratch ----------------
__device__ float          g_xT[BB*HH*WW*CIN];          // NHWC input
__device__ __nv_bfloat16  g_wA[NCHUNK*2*256*72];       // [q][hi/lo][o 256][72]
__device__ float4         g_params[BB*NP*KK9];
__device__ float          g_pre[BB*COUT*NP];
__device__ float2         g_ps[NCTA2*COUT];
__device__ float          g_bn[2*COUT];

// ---------------- PTX helpers (baseline sm_103-legal) ----------------
__device__ __forceinline__ uint32_t smem_u32(const void* p) {
    uint32_t a;
    asm("{ .reg .u64 t; cvta.to.shared.u64 t, %1; cvt.u32.u64 %0, t; }" : "=r"(a) : "l"(p));
    return a;
}
__device__ __forceinline__ void ldsm4(uint32_t* r, uint32_t addr) {
    asm volatile("ldmatrix.sync.aligned.m8n8.x4.shared.b16 {%0,%1,%2,%3}, [%4];"
        : "=r"(r[0]), "=r"(r[1]), "=r"(r[2]), "=r"(r[3]) : "r"(addr));
}
__device__ __forceinline__ void mma16816(float* d, const uint32_t* a, uint32_t b0, uint32_t b1) {
    asm volatile("mma.sync.aligned.m16n8k16.row.col.f32.bf16.bf16.f32 "
        "{%0,%1,%2,%3}, {%4,%5,%6,%7}, {%8,%9}, {%0,%1,%2,%3};"
        : "+f"(d[0]), "+f"(d[1]), "+f"(d[2]), "+f"(d[3])
        : "r"(a[0]), "r"(a[1]), "r"(a[2]), "r"(a[3]), "r"(b0), "r"(b1));
}
__device__ __forceinline__ void cpa16(uint32_t dst, const void* src) {
    asm volatile("cp.async.cg.shared.global [%0], [%1], 16;" :: "r"(dst), "l"(src));
}
__device__ __forceinline__ void cpa_commit() {
    asm volatile("cp.async.commit_group;" ::: "memory");
}
template <int N>
__device__ __forceinline__ void cpa_wait() {
    asm volatile("cp.async.wait_group %0;" :: "n"(N) : "memory");
}

// ---------------- K0: vectorized tiled transpose (B,C,H,W)->(B,H,W,C) ----------------
__global__ __launch_bounds__(256) void k_transpose(const float* __restrict__ x) {
    int b = blockIdx.x / HH;
    int y = blockIdx.x % HH;
    __shared__ float4 s4[CIN*21];
    const float4* src = (const float4*)(x + ((size_t)b*CIN)*HH*WW + (size_t)y*WW);
    int tid = threadIdx.x;
    #pragma unroll
    for (int i = 0; i < 10; i++) {
        int idx = tid + i*256;
        int c = idx / 20, w4 = idx % 20;
        s4[c*21 + w4] = src[(size_t)c*1600 + w4];
    }
    __syncthreads();
    const float* sf = (const float*)s4;
    float4* dst = (float4*)&g_xT[((size_t)(b*HH + y))*WW*CIN];
    #pragma unroll
    for (int i = 0; i < 10; i++) {
        int idx = tid + i*256;
        int w  = idx >> 5;
        int c4 = (idx & 31)*4;
        int base = w >> 2, wm = (w & 3);
        float4 v;
        v.x = sf[(c4+0)*84 + base*4 + wm];
        v.y = sf[(c4+1)*84 + base*4 + wm];
        v.z = sf[(c4+2)*84 + base*4 + wm];
        v.w = sf[(c4+3)*84 + base*4 + wm];
        dst[idx] = v;
    }
}

// ---------------- K0b: weight prep -> padded bf16 hi/lo tiles (merged M) ----------------
__global__ void k_wprep(const float* __restrict__ w) {
    int i = blockIdx.x*256 + threadIdx.x;
    if (i >= NCHUNK*2*256*72) return;
    int u  = i % 72;
    int t1 = i / 72;
    int o  = t1 & 255;
    int t2 = t1 >> 8;
    int hl = t2 & 1;
    int q  = t2 >> 1;
    __nv_bfloat16 outv = __float2bfloat16(0.f);
    if (u < 64) {
        int tap = q >> 1;
        int c   = ((q & 1) << 6) | u;
        float v = w[(size_t)o*RED + c*KK9 + tap];
        __nv_bfloat16 h = __float2bfloat16(v);
        outv = hl ? __float2bfloat16(v - __bfloat162float(h)) : h;
    }
    g_wA[i] = outv;
}

// ---------------- K1: offsets + bilinear params ----------------
__global__ void k_offsets(const float* __restrict__ offw, const float* __restrict__ offb) {
    int gw   = (blockIdx.x * blockDim.x + threadIdx.x) >> 5;
    int lane = threadIdx.x & 31;
    if (gw >= BB*NP) return;
    int b = gw / NP, p = gw % NP;
    int ho = p / WO, wo = p % WO;

    const float4* xs = (const float4*)&g_xT[(((size_t)b*HH + 2*ho)*WW + 2*wo)*CIN];
    float4 xv = xs[lane];

    float dy = 0.f, dx = 0.f;
    #pragma unroll
    for (int j = 0; j < 18; j++) {
        const float* wr = offw + j*CIN + lane*4;
        float s = wr[0]*xv.x + wr[1]*xv.y + wr[2]*xv.z + wr[3]*xv.w;
        #pragma unroll
        for (int d = 16; d > 0; d >>= 1) s += __shfl_xor_sync(0xffffffffu, s, d);
        if (lane < 9) {
            if (j == 2*lane)     dy = s;
            if (j == 2*lane + 1) dx = s;
        }
    }
    if (lane < 9) {
        int k = lane;
        dy += __ldg(&offb[2*k]);
        dx += __ldg(&offb[2*k+1]);
        float py = (float)(ho*2 - 1 + k/3) + dy;
        float px = (float)(wo*2 - 1 + k%3) + dx;
        float fy = floorf(py), fx = floorf(px);
        int y0 = (int)fy, x0 = (int)fx;
        g_params[(size_t)gw*KK9 + k] =
            make_float4(__int_as_float(y0), __int_as_float(x0), py - fy, px - fx);
    }
}

// ---------------- K2: main — merged-M pipelined gather + warp-MMA ----------------
// 400 CTAs: (b, ptile of 64). 256 threads, 8 warps each m32 x n64, full M=256.
__global__ __launch_bounds__(256, 1) void k_main(const float* __restrict__ deform_b) {
    extern __shared__ __align__(16) unsigned char sm[];
    uint32_t sb = smem_u32(sm);
    int tid  = threadIdx.x;
    int wid  = tid >> 5;
    int lane = tid & 31;
    int bid  = blockIdx.x;
    int pt   = bid % NPT;
    int b    = bid / NPT;
    int wm   = wid;

    float4* spb = (float4*)(sm + SM_PAR);   // [tap][pos]
    const float* xb = &g_xT[(size_t)b*HH*WW*CIN];
    int c16 = tid & 15;
    int pst = tid >> 4;

    // ldmatrix lane addresses (buffer-0 relative)
    uint32_t aadr0 = sb + SM_A0 + (uint32_t)(wm*32 + (lane & 15))*ROWB + ((lane >> 4) & 1)*16;
    uint32_t aadr1 = aadr0 + 16*ROWB;
    uint32_t badr  = sb + SM_B0 + (uint32_t)((lane & 7) + ((lane >> 4) & 1)*8)*ROWB
                   + ((lane >> 3) & 1)*16;

    float d[2][8][4];
    #pragma unroll
    for (int mf = 0; mf < 2; mf++)
        #pragma unroll
        for (int nf = 0; nf < 8; nf++)
            #pragma unroll
            for (int j = 0; j < 4; j++) d[mf][nf][j] = 0.f;

    // ---- prologue ----
    for (int i = tid; i < KK9*NT; i += 256) {
        int p = i / KK9, tap = i - p*KK9;
        spb[tap*NT + p] = g_params[((size_t)b*NP + pt*NT + p)*KK9 + tap];
    }
    // cp.async A(0)->A0, A(1)->A1  (18 x 16B per thread each)
    #pragma unroll
    for (int qq = 0; qq < 2; qq++) {
        const char* asrc = (const char*)g_wA + (size_t)qq*ABUF;
        uint32_t adst = sb + (qq ? SM_A1 : SM_A0);
        #pragma unroll
        for (int i = 0; i < 18; i++) {
            uint32_t off = (uint32_t)(tid + i*256)*16;
            cpa16(adst + off, asrc + off);
        }
        cpa_commit();
    }
    __syncthreads();   // params visible

    float4 G[4][4];
    // gather + convert + STS chunk 0 -> B0
    {
        int cb = c16*4;
        const float4* sp_tap = (const float4*)&spb[0];
        #pragma unroll
        for (int it = 0; it < 4; it++) {
            int p = pst + it*16;
            float4 pr = sp_tap[p];
            int y0 = __float_as_int(pr.x);
            int x0 = __float_as_int(pr.y);
            int y1 = y0 + 1, x1 = x0 + 1;
            bool vy0 = ((unsigned)y0 < (unsigned)HH);
            bool vy1 = ((unsigned)y1 < (unsigned)HH);
            bool vx0 = ((unsigned)x0 < (unsigned)WW);
            bool vx1 = ((unsigned)x1 < (unsigned)WW);
            int yc0 = min(max(y0, 0), HH-1), yc1 = min(max(y1, 0), HH-1);
            int xc0 = min(max(x0, 0), WW-1), xc1 = min(max(x1, 0), WW-1);
            const float4 z4 = make_float4(0.f, 0.f, 0.f, 0.f);
            G[it][0] = (vy0 && vx0) ? *(const float4*)(xb + ((size_t)yc0*WW + xc0)*CIN + cb) : z4;
            G[it][1] = (vy0 && vx1) ? *(const float4*)(xb + ((size_t)yc0*WW + xc1)*CIN + cb) : z4;
            G[it][2] = (vy1 && vx0) ? *(const float4*)(xb + ((size_t)yc1*WW + xc0)*CIN + cb) : z4;
            G[it][3] = (vy1 && vx1) ? *(const float4*)(xb + ((size_t)yc1*WW + xc1)*CIN + cb) : z4;
        }
        unsigned char* bbase = sm + SM_B0;
        #pragma unroll
        for (int it = 0; it < 4; it++) {
            int p = pst + it*16;
            float4 pr = sp_tap[p];
            float wy1 = pr.z, wx1 = pr.w;
            float wy0 = 1.f - wy1, wx0 = 1.f - wx1;
            float w00 = wy0*wx0, w01 = wy0*wx1, w10 = wy1*wx0, w11 = wy1*wx1;
            float v0 = w00*G[it][0].x + w01*G[it][1].x + w10*G[it][2].x + w11*G[it][3].x;
            float v1 = w00*G[it][0].y + w01*G[it][1].y + w10*G[it][2].y + w11*G[it][3].y;
            float v2 = w00*G[it][0].z + w01*G[it][1].z + w10*G[it][2].z + w11*G[it][3].z;
            float v3 = w00*G[it][0].w + w01*G[it][1].w + w10*G[it][2].w + w11*G[it][3].w;
            __nv_bfloat16 h0 = __float2bfloat16(v0), h1 = __float2bfloat16(v1);
            __nv_bfloat16 h2 = __float2bfloat16(v2), h3 = __float2bfloat16(v3);
            float l0 = v0 - __bfloat162float(h0), l1 = v1 - __bfloat162float(h1);
            float l2 = v2 - __bfloat162float(h2), l3 = v3 - __bfloat162float(h3);
            unsigned long long hv =
                (unsigned long long)__bfloat16_as_ushort(h0)
              | ((unsigned long long)__bfloat16_as_ushort(h1) << 16)
              | ((unsigned long long)__bfloat16_as_ushort(h2) << 32)
              | ((unsigned long long)__bfloat16_as_ushort(h3) << 48);
            unsigned long long lv =
                (unsigned long long)__bfloat16_as_ushort(__float2bfloat16(l0))
              | ((unsigned long long)__bfloat16_as_ushort(__float2bfloat16(l1)) << 16)
              | ((unsigned long long)__bfloat16_as_ushort(__float2bfloat16(l2)) << 32)
              | ((unsigned long long)__bfloat16_as_ushort(__float2bfloat16(l3)) << 48);
            uint32_t off = (uint32_t)p*ROWB + c16*8;
            *(unsigned long long*)(bbase + off) = hv;
            *(unsigned long long*)(bbase + BTILEB + off) = lv;
        }
    }
    cpa_wait<1>();       // A(0) ready
    __syncthreads();

    // ---- main pipelined loop ----
    #pragma unroll 1
    for (int q = 0; q < NCHUNK; q++) {
        // stage LDGs for chunk q+1 (overlaps MMA below)
        if (q < NCHUNK-1) {
            int qq = q + 1;
            int cb = ((qq & 1) << 6) + c16*4;
            const float4* sp_tap = (const float4*)&spb[(qq >> 1)*NT];
            #pragma unroll
            for (int it = 0; it < 4; it++) {
                int p = pst + it*16;
                float4 pr = sp_tap[p];
                int y0 = __float_as_int(pr.x);
                int x0 = __float_as_int(pr.y);
                int y1 = y0 + 1, x1 = x0 + 1;
                bool vy0 = ((unsigned)y0 < (unsigned)HH);
                bool vy1 = ((unsigned)y1 < (unsigned)HH);
                bool vx0 = ((unsigned)x0 < (unsigned)WW);
                bool vx1 = ((unsigned)x1 < (unsigned)WW);
                int yc0 = min(max(y0, 0), HH-1), yc1 = min(max(y1, 0), HH-1);
                int xc0 = min(max(x0, 0), WW-1), xc1 = min(max(x1, 0), WW-1);
                const float4 z4 = make_float4(0.f, 0.f, 0.f, 0.f);
                G[it][0] = (vy0 && vx0) ? *(const float4*)(xb + ((size_t)yc0*WW + xc0)*CIN + cb) : z4;
                G[it][1] = (vy0 && vx1) ? *(const float4*)(xb + ((size_t)yc0*WW + xc1)*CIN + cb) : z4;
                G[it][2] = (vy1 && vx0) ? *(const float4*)(xb + ((size_t)yc1*WW + xc0)*CIN + cb) : z4;
                G[it][3] = (vy1 && vx1) ? *(const float4*)(xb + ((size_t)yc1*WW + xc1)*CIN + cb) : z4;
            }
        }

        // MMA chunk q
        {
            uint32_t aoff = (q & 1) ? (uint32_t)(SM_A1 - SM_A0) : 0u;
            uint32_t boff = (q & 1) ? (uint32_t)(SM_B1 - SM_B0) : 0u;
            #pragma unroll
            for (int kf = 0; kf < 4; kf++) {
                uint32_t kb = kf*32;
                uint32_t Ah0[4], Ah1[4], Al0[4], Al1[4];
                ldsm4(Ah0, aadr0 + aoff + kb);
                ldsm4(Ah1, aadr1 + aoff + kb);
                ldsm4(Al0, aadr0 + aoff + ATILEB + kb);
                ldsm4(Al1, aadr1 + aoff + ATILEB + kb);
                #pragma unroll
                for (int g = 0; g < 4; g++) {
                    uint32_t Bh[4], Bl[4];
                    ldsm4(Bh, badr + boff + (uint32_t)g*16*ROWB + kb);
                    ldsm4(Bl, badr + boff + BTILEB + (uint32_t)g*16*ROWB + kb);
                    #pragma unroll
                    for (int mf = 0; mf < 2; mf++) {
                        const uint32_t* ah = mf ? Ah1 : Ah0;
                        const uint32_t* al = mf ? Al1 : Al0;
                        #pragma unroll
                        for (int h = 0; h < 2; h++) {
                            int nf = g*2 + h;
                            mma16816(d[mf][nf], ah, Bh[h*2], Bh[h*2+1]);
                            mma16816(d[mf][nf], ah, Bl[h*2], Bl[h*2+1]);
                            mma16816(d[mf][nf], al, Bh[h*2], Bh[h*2+1]);
                        }
                    }
                }
            }
        }
        __syncthreads();   // MMA q complete block-wide

        // convert + STS chunk q+1; prefetch A(q+2) into the buffer MMA just freed
        if (q < NCHUNK-1) {
            int qq = q + 1;
            const float4* sp_tap = (const float4*)&spb[(qq >> 1)*NT];
            unsigned char* bbase = sm + ((qq & 1) ? SM_B1 : SM_B0);
            #pragma unroll
            for (int it = 0; it < 4; it++) {
                int p = pst + it*16;
                float4 pr = sp_tap[p];
                float wy1 = pr.z, wx1 = pr.w;
                float wy0 = 1.f - wy1, wx0 = 1.f - wx1;
                float w00 = wy0*wx0, w01 = wy0*wx1, w10 = wy1*wx0, w11 = wy1*wx1;
                float v0 = w00*G[it][0].x + w01*G[it][1].x + w10*G[it][2].x + w11*G[it][3].x;
                float v1 = w00*G[it][0].y + w01*G[it][1].y + w10*G[it][2].y + w11*G[it][3].y;
                float v2 = w00*G[it][0].z + w01*G[it][1].z + w10*G[it][2].z + w11*G[it][3].z;
                float v3 = w00*G[it][0].w + w01*G[it][1].w + w10*G[it][2].w + w11*G[it][3].w;
                __nv_bfloat16 h0 = __float2bfloat16(v0), h1 = __float2bfloat16(v1);
                __nv_bfloat16 h2 = __float2bfloat16(v2), h3 = __float2bfloat16(v3);
                float l0 = v0 - __bfloat162float(h0), l1 = v1 - __bfloat162float(h1);
                float l2 = v2 - __bfloat162float(h2), l3 = v3 - __bfloat162float(h3);
                unsigned long long hv =
                    (unsigned long long)__bfloat16_as_ushort(h0)
                  | ((unsigned long long)__bfloat16_as_ushort(h1) << 16)
                  | ((unsigned long long)__bfloat16_as_ushort(h2) << 32)
                  | ((unsigned long long)__bfloat16_as_ushort(h3) << 48);
                unsigned long long lv =
                    (unsigned long long)__bfloat16_as_ushort(__float2bfloat16(l0))
                  | ((unsigned long long)__bfloat16_as_ushort(__float2bfloat16(l1)) << 16)
                  | ((unsigned long long)__bfloat16_as_ushort(__float2bfloat16(l2)) << 32)
                  | ((unsigned long long)__bfloat16_as_ushort(__float2bfloat16(l3)) << 48);
                uint32_t off = (uint32_t)p*ROWB + c16*8;
                *(unsigned long long*)(bbase + off) = hv;
                *(unsigned long long*)(bbase + BTILEB + off) = lv;
            }
        }
        if (q + 2 < NCHUNK) {
            int qq = q + 2;
            const char* asrc = (const char*)g_wA + (size_t)qq*ABUF;
            uint32_t adst = sb + ((qq & 1) ? SM_A1 : SM_A0);
            #pragma unroll
            for (int i = 0; i < 18; i++) {
                uint32_t off = (uint32_t)(tid + i*256)*16;
                cpa16(adst + off, asrc + off);
            }
            cpa_commit();
            cpa_wait<1>();       // A(q+1) ready
        } else {
            cpa_wait<0>();
        }
        __syncthreads();   // STS visible + A(q+1) ready
    }

    // ---- epilogue: bias + store + BN partials ----
    int rbase = lane >> 2;
    int cpair = (lane & 3)*2;
    #pragma unroll
    for (int mf = 0; mf < 2; mf++) {
        #pragma unroll
        for (int rh = 0; rh < 2; rh++) {
            int o = wm*32 + mf*16 + rh*8 + rbase;
            float bias = __ldg(&deform_b[o]);
            float s1 = 0.f, s2 = 0.f;
            float* orow = &g_pre[((size_t)(b*COUT + o))*NP + pt*NT];
            #pragma unroll
            for (int nf = 0; nf < 8; nf++) {
                float v0 = d[mf][nf][rh*2 + 0] + bias;
                float v1 = d[mf][nf][rh*2 + 1] + bias;
                *(float2*)&orow[nf*8 + cpair] = make_float2(v0, v1);
                s1 += v0 + v1;
                s2 += v0*v0 + v1*v1;
            }
            s1 += __shfl_xor_sync(0xffffffffu, s1, 1);
            s1 += __shfl_xor_sync(0xffffffffu, s1, 2);
            s2 += __shfl_xor_sync(0xffffffffu, s2, 1);
            s2 += __shfl_xor_sync(0xffffffffu, s2, 2);
            if ((lane & 3) == 0)
                g_ps[((size_t)(b*NPT + pt))*COUT + o] = make_float2(s1, s2);
        }
    }
}

// ---------------- K3: BN finalize (parallel, deterministic) ----------------
__global__ void k_bnfin(const float* __restrict__ gamma, const float* __restrict__ beta) {
    int o = blockIdx.x;
    int tid = threadIdx.x;     // 128
    double s = 0.0, s2 = 0.0;
    for (int t = tid; t < NCTA2; t += 128) {
        float2 v = g_ps[(size_t)t*COUT + o];
        s  += (double)v.x;
        s2 += (double)v.y;
    }
    __shared__ double sh[128], sh2[128];
    sh[tid] = s; sh2[tid] = s2;
    __syncthreads();
    for (int dd = 64; dd > 0; dd >>= 1) {
        if (tid < dd) { sh[tid] += sh[tid+dd]; sh2[tid] += sh2[tid+dd]; }
        __syncthreads();
    }
    if (tid == 0) {
        const double N = (double)(BB*NP);
        double mean = sh[0] / N;
        double var  = sh2[0] / N - mean*mean;
        double inv  = 1.0 / sqrt(var + 1e-5);
        float scale = (float)((double)gamma[o] * inv);
        float shift = (float)((double)beta[o] - mean * (double)scale);
        g_bn[2*o]   = scale;
        g_bn[2*o+1] = shift;
    }
}

// ---------------- K4: fused BN + SiLU ----------------
__global__ void k_act(float* __restrict__ out) {
    int i = blockIdx.x*256 + threadIdx.x;
    const int NV = BB*COUT*NP/4;
    if (i >= NV) return;
    int e = i*4;
    int o = (e / NP) & (COUT-1);
    float sc = g_bn[2*o], sh = g_bn[2*o+1];
    float4 v = ((const float4*)g_pre)[i];
    float y0 = v.x*sc + sh;
    float y1 = v.y*sc + sh;
    float y2 = v.z*sc + sh;
    float y3 = v.w*sc + sh;
    v.x = y0 / (1.f + __expf(-y0));
    v.y = y1 / (1.f + __expf(-y1));
    v.z = y2 / (1.f + __expf(-y2));
    v.w = y3 / (1.f + __expf(-y3));
    ((float4*)out)[i] = v;
}

// ---------------- launch ----------------
extern "C" void kernel_launch(void* const* d_in, const int* in_sizes, int n_in,
                              void* d_out, int out_size) {
    const float* x        = (const float*)d_in[0];
    const float* offset_w = (const float*)d_in[1];
    const float* offset_b = (const float*)d_in[2];
    const float* deform_w = (const float*)d_in[3];
    const float* deform_b = (const float*)d_in[4];
    const float* bn_gamma = (const float*)d_in[5];
    const float* bn_beta  = (const float*)d_in[6];
    float* out = (float*)d_out;

    cudaFuncSetAttribute(k_main, cudaFuncAttributeMaxDynamicSharedMemorySize, SM_TOTAL);

    k_transpose<<<BB*HH, 256>>>(x);
    k_wprep<<<(NCHUNK*2*256*72 + 255)/256, 256>>>(deform_w);
    k_offsets<<<(BB*NP*32 + 127)/128, 128>>>(offset_w, offset_b);
    k_main<<<NCTA2, 256, SM_TOTAL>>>(deform_b);
    k_bnfin<<<COUT, 128>>>(bn_gamma, bn_beta);
    k_act<<<(BB*COUT*NP/4 + 255)/256, 256>>>(out);
}